// round 7
// baseline (speedup 1.0000x reference)
#include <cuda_runtime.h>
#include <math.h>

// B=256, T=512, C=512, L=64
#define BN 256
#define TN 512
#define CN 512
#define LN 64
#define SN 129              // 2L+1
#define BLANK 511
#define EPSV 1e-7f
#define RS 16               // ring slots per chain (deep memory cover)
#define KS 5                // states per lane per chain
#define LN2F 0.6931471805599453f
#define FULL 0xffffffffu

// CTC forward DP: one warp handles TWO batch elements (independent chains
// interleaved for ILP). Alpha in registers (5/lane/chain), neighbors via
// shfl. Each chain streams its rows through a 16-slot cp.async ring; one
// commit group per step covers both chains. Wait at loop top (round-4
// structure, which measured best). Linear space + exact 2^-e renorm.
__global__ __launch_bounds__(32, 3)
void ctc_dual_kernel(const int* __restrict__ labels,     // [B, L]
                     const float* __restrict__ y_pred,   // [B, T, C]
                     const int* __restrict__ in_len,     // [B, 1]
                     const int* __restrict__ lab_len,    // [B, 1]
                     float* __restrict__ out)            // [B, 1]
{
    const int lane = threadIdx.x;
    const int bb   = blockIdx.x * 2;      // chains handle bb, bb+1

    __shared__ __align__(16) float rows[2][RS][CN];   // 64KB ring
    __shared__ float fin[2][SN];
    __shared__ int   ecap_sh[2];

    // ---- per-chain static state ----
    int  cls[2][KS];
    bool valid[KS];
    bool alw[2][KS];

    #pragma unroll
    for (int j = 0; j < KS; ++j) {
        int s = KS * lane + j;
        valid[j] = (s < SN);
    }
    #pragma unroll
    for (int c = 0; c < 2; ++c) {
        const int b = bb + c;
        #pragma unroll
        for (int j = 0; j < KS; ++j) {
            int s = KS * lane + j;
            int cl = BLANK;
            if (valid[j] && (s & 1)) cl = labels[b * LN + (s >> 1)];
            cls[c][j] = valid[j] ? cl : 0;
        }
        int cu2 = __shfl_up_sync(FULL, cls[c][KS - 2], 1);
        int cu1 = __shfl_up_sync(FULL, cls[c][KS - 1], 1);
        #pragma unroll
        for (int j = 0; j < KS; ++j) {
            int s   = KS * lane + j;
            int cm2 = (j >= 2) ? cls[c][j - 2] : ((j == 1) ? cu1 : cu2);
            alw[c][j] = valid[j] && (s >= 2) && (cls[c][j] != BLANK) && (cls[c][j] != cm2);
        }
    }

    const float* base[2] = { y_pred + (size_t)bb * TN * CN,
                             y_pred + (size_t)(bb + 1) * TN * CN };
    const int Te[2] = { in_len[bb], in_len[bb + 1] };

    // ---- t = 0 ----
    float a0[KS], a1[KS];
    #pragma unroll
    for (int j = 0; j < KS; ++j) {
        int s = KS * lane + j;
        a0[j] = (s < 2) ? (base[0][cls[0][j]] + EPSV) : 0.0f;
        a1[j] = (s < 2) ? (base[1][cls[1][j]] + EPSV) : 0.0f;
    }
    #pragma unroll
    for (int c = 0; c < 2; ++c) {
        if (Te[c] == 1) {
            #pragma unroll
            for (int j = 0; j < KS; ++j)
                if (valid[j]) fin[c][KS * lane + j] = (c == 0) ? a0[j] : a1[j];
            if (lane == 0) ecap_sh[c] = 0;
        }
    }

    // ---- prologue: rows 1..RS-1 for both chains, one group per stage ----
    #pragma unroll
    for (int st = 1; st < RS; ++st) {
        #pragma unroll
        for (int c = 0; c < 2; ++c) {
            #pragma unroll
            for (int k = 0; k < 4; ++k) {
                unsigned dst = (unsigned)__cvta_generic_to_shared(
                    &rows[c][st & (RS - 1)][lane * 4 + k * 128]);
                const float* src = base[c] + (size_t)st * CN + lane * 4 + k * 128;
                asm volatile("cp.async.cg.shared.global [%0], [%1], 16;"
                             :: "r"(dst), "l"(src));
            }
        }
        asm volatile("cp.async.commit_group;");
    }

    int   E[2] = {0, 0}, pend_e[2] = {0, 0};
    float pend_sc[2] = {1.0f, 1.0f};

    #pragma unroll 4
    for (int t = 1; t < TN; ++t) {
        asm volatile("cp.async.wait_group %0;" :: "n"(RS - 2)); // rows t ready
        __syncwarp();

        // refill slot (t-1)&(RS-1) with row t+RS-1 (both chains, one group)
        {
            int st = t + RS - 1;
            if (st < TN) {
                #pragma unroll
                for (int c = 0; c < 2; ++c) {
                    #pragma unroll
                    for (int k = 0; k < 4; ++k) {
                        unsigned dst = (unsigned)__cvta_generic_to_shared(
                            &rows[c][st & (RS - 1)][lane * 4 + k * 128]);
                        const float* src = base[c] + (size_t)st * CN + lane * 4 + k * 128;
                        asm volatile("cp.async.cg.shared.global [%0], [%1], 16;"
                                     :: "r"(dst), "l"(src));
                    }
                }
            }
            asm volatile("cp.async.commit_group;");   // keep group count uniform
        }

        float sc0  = 512.0f * pend_sc[0];
        float ep0  = (512.0f * EPSV) * pend_sc[0];
        float sc1  = 512.0f * pend_sc[1];
        float ep1  = (512.0f * EPSV) * pend_sc[1];
        E[0] += pend_e[0]; E[1] += pend_e[1];
        pend_e[0] = pend_e[1] = 0;
        pend_sc[0] = pend_sc[1] = 1.0f;

        // gathers for both chains (independent -> LSU pipelining)
        const float* r0 = rows[0][t & (RS - 1)];
        const float* r1 = rows[1][t & (RS - 1)];
        float pe0[KS], pe1[KS];
        #pragma unroll
        for (int j = 0; j < KS; ++j) {
            pe0[j] = valid[j] ? fmaf(r0[cls[0][j]], sc0, ep0) : 0.0f;
            pe1[j] = valid[j] ? fmaf(r1[cls[1][j]], sc1, ep1) : 0.0f;
        }

        float h1a = __shfl_up_sync(FULL, a0[KS - 1], 1);
        float h2a = __shfl_up_sync(FULL, a0[KS - 2], 1);
        float h1b = __shfl_up_sync(FULL, a1[KS - 1], 1);
        float h2b = __shfl_up_sync(FULL, a1[KS - 2], 1);
        if (lane == 0) { h1a = h2a = h1b = h2b = 0.0f; }

        {
            float n0 = (a0[0] + h1a   + (alw[0][0] ? h2a   : 0.0f)) * pe0[0];
            float n1 = (a0[1] + a0[0] + (alw[0][1] ? h1a   : 0.0f)) * pe0[1];
            float n2 = (a0[2] + a0[1] + (alw[0][2] ? a0[0] : 0.0f)) * pe0[2];
            float n3 = (a0[3] + a0[2] + (alw[0][3] ? a0[1] : 0.0f)) * pe0[3];
            float n4 = (a0[4] + a0[3] + (alw[0][4] ? a0[2] : 0.0f)) * pe0[4];
            a0[0] = n0; a0[1] = n1; a0[2] = n2; a0[3] = n3; a0[4] = n4;
        }
        {
            float n0 = (a1[0] + h1b   + (alw[1][0] ? h2b   : 0.0f)) * pe1[0];
            float n1 = (a1[1] + a1[0] + (alw[1][1] ? h1b   : 0.0f)) * pe1[1];
            float n2 = (a1[2] + a1[1] + (alw[1][2] ? a1[0] : 0.0f)) * pe1[2];
            float n3 = (a1[3] + a1[2] + (alw[1][3] ? a1[1] : 0.0f)) * pe1[3];
            float n4 = (a1[4] + a1[3] + (alw[1][4] ? a1[2] : 0.0f)) * pe1[4];
            a1[0] = n0; a1[1] = n1; a1[2] = n2; a1[3] = n3; a1[4] = n4;
        }

        if ((t & 7) == 0) {
            unsigned u0 = __float_as_uint(a0[0]);
            u0 = max(u0, __float_as_uint(a0[1]));
            u0 = max(u0, __float_as_uint(a0[2]));
            u0 = max(u0, __float_as_uint(a0[3]));
            u0 = max(u0, __float_as_uint(a0[4]));
            unsigned u1 = __float_as_uint(a1[0]);
            u1 = max(u1, __float_as_uint(a1[1]));
            u1 = max(u1, __float_as_uint(a1[2]));
            u1 = max(u1, __float_as_uint(a1[3]));
            u1 = max(u1, __float_as_uint(a1[4]));
            u0 = __reduce_max_sync(FULL, u0);
            u1 = __reduce_max_sync(FULL, u1);
            int e0 = (int)(u0 >> 23) - 127;
            int e1 = (int)(u1 >> 23) - 127;
            pend_e[0] = e0;
            pend_e[1] = e1;
            pend_sc[0] = __uint_as_float((unsigned)(127 - e0) << 23);  // 2^-e
            pend_sc[1] = __uint_as_float((unsigned)(127 - e1) << 23);
        }

        if (t == Te[0] - 1) {
            #pragma unroll
            for (int j = 0; j < KS; ++j)
                if (valid[j]) fin[0][KS * lane + j] = a0[j];
            if (lane == 0) ecap_sh[0] = E[0];
        }
        if (t == Te[1] - 1) {
            #pragma unroll
            for (int j = 0; j < KS; ++j)
                if (valid[j]) fin[1][KS * lane + j] = a1[j];
            if (lane == 0) ecap_sh[1] = E[1];
        }
    }
    __syncwarp();

    if (lane < 2) {
        const int c = lane;
        int ll = lab_len[bb + c];
        int i1 = 2 * ll;
        int i2 = 2 * ll - 1;
        if (i1 < 0) i1 += SN;
        if (i2 < 0) i2 += SN;
        float x = fin[c][i1] + fin[c][i2];
        out[bb + c] = -logf(x) + ((float)(9 * (Te[c] - 1) - ecap_sh[c])) * LN2F;
    }
}

extern "C" void kernel_launch(void* const* d_in, const int* in_sizes, int n_in,
                              void* d_out, int out_size)
{
    const int*   y_true       = (const int*)d_in[0];
    const float* y_pred       = (const float*)d_in[1];
    const int*   input_length = (const int*)d_in[2];
    const int*   label_length = (const int*)d_in[3];
    float*       out          = (float*)d_out;

    ctc_dual_kernel<<<BN / 2, 32>>>(y_true, y_pred, input_length, label_length, out);
}

// round 8
// speedup vs baseline: 1.6217x; 1.6217x over previous
#include <cuda_runtime.h>
#include <math.h>

// B=256, T=512, C=512, L=64
#define BN 256
#define TN 512
#define CN 512
#define LN 64
#define SN 129              // 2L+1
#define BLANK 511
#define EPSV 1e-7f
#define RS 10               // ring slots per warp
#define WAITN 7             // outstanding groups: rows <= t+1 complete at top
#define KS 5                // states per lane
#define LN2F 0.6931471805599453f
#define FULL 0xffffffffu

// CTC forward DP: 2 warps per CTA, each warp = one batch element with its
// own cp.async ring (so the two warps land on different SMSPs — no shared
// scheduler/LSU). Alpha in registers (5/lane), neighbors via shfl.
// The smem gather for step t+1 is prefetched at step t (wait_group 7 with a
// 10-slot ring guarantees row t+1 resident), hiding LDS latency + bank
// conflicts. Linear space + exact power-of-2 renorm (same math as logsumexp).
__global__ __launch_bounds__(64, 1)
void ctc_w2_kernel(const int* __restrict__ labels,     // [B, L]
                   const float* __restrict__ y_pred,   // [B, T, C]
                   const int* __restrict__ in_len,     // [B, 1]
                   const int* __restrict__ lab_len,    // [B, 1]
                   float* __restrict__ out)            // [B, 1]
{
    const int lane = threadIdx.x & 31;
    const int w    = threadIdx.x >> 5;          // 0 or 1
    const int b    = blockIdx.x * 2 + w;

    __shared__ __align__(16) float rows[2][RS][CN];   // ~40KB
    __shared__ float fin[2][SN];
    __shared__ int   ecap_sh[2];

    // Extended labels: state s = KS*lane + j
    int  cls[KS];
    bool valid[KS];
    #pragma unroll
    for (int j = 0; j < KS; ++j) {
        int s = KS * lane + j;
        valid[j] = (s < SN);
        int c = BLANK;
        if (valid[j] && (s & 1)) c = labels[b * LN + (s >> 1)];
        cls[j] = valid[j] ? c : 0;
    }
    int cu2 = __shfl_up_sync(FULL, cls[KS - 2], 1);
    int cu1 = __shfl_up_sync(FULL, cls[KS - 1], 1);
    bool alw[KS];
    #pragma unroll
    for (int j = 0; j < KS; ++j) {
        int s   = KS * lane + j;
        int cm2 = (j >= 2) ? cls[j - 2] : ((j == 1) ? cu1 : cu2);
        alw[j] = valid[j] && (s >= 2) && (cls[j] != BLANK) && (cls[j] != cm2);
    }

    const float* base  = y_pred + (size_t)b * TN * CN;
    const int    T_eff = in_len[b];

    // t = 0
    float a[KS];
    #pragma unroll
    for (int j = 0; j < KS; ++j) {
        int s = KS * lane + j;
        a[j] = (s < 2) ? (base[cls[j]] + EPSV) : 0.0f;
    }
    if (T_eff == 1) {
        #pragma unroll
        for (int j = 0; j < KS; ++j)
            if (valid[j]) fin[w][KS * lane + j] = a[j];
        if (lane == 0) ecap_sh[w] = 0;
    }

    // Prologue: rows 1..RS-1 into this warp's ring (per-warp commit groups)
    #pragma unroll
    for (int st = 1; st < RS; ++st) {
        #pragma unroll
        for (int k = 0; k < 4; ++k) {
            unsigned dst = (unsigned)__cvta_generic_to_shared(
                &rows[w][st % RS][lane * 4 + k * 128]);
            const float* src = base + (size_t)st * CN + lane * 4 + k * 128;
            asm volatile("cp.async.cg.shared.global [%0], [%1], 16;"
                         :: "r"(dst), "l"(src));
        }
        asm volatile("cp.async.commit_group;");
    }

    // Initial gather: raw probs of row 1 (9 groups committed, wait<=7 -> rows<=2 done)
    float praw[KS];
    asm volatile("cp.async.wait_group %0;" :: "n"(WAITN));
    __syncwarp();
    {
        const float* row = rows[w][1];
        #pragma unroll
        for (int j = 0; j < KS; ++j) praw[j] = row[cls[j]];
    }

    int   E = 0, pend_e = 0;
    float pend_sc = 1.0f;
    int   slot = 1;           // slot of row t (t % RS), maintained incrementally

    #pragma unroll 5
    for (int t = 1; t < TN; ++t) {
        // committed rows <= t+RS-2 ; wait<=WAITN -> rows <= t+1 complete
        asm volatile("cp.async.wait_group %0;" :: "n"(WAITN));
        __syncwarp();

        // refill: row t+RS-1 -> slot (t-1)%RS
        {
            int st = t + RS - 1;
            int wsl = slot - 1; if (wsl < 0) wsl += RS;
            if (st < TN) {
                #pragma unroll
                for (int k = 0; k < 4; ++k) {
                    unsigned dst = (unsigned)__cvta_generic_to_shared(
                        &rows[w][wsl][lane * 4 + k * 128]);
                    const float* src = base + (size_t)st * CN + lane * 4 + k * 128;
                    asm volatile("cp.async.cg.shared.global [%0], [%1], 16;"
                                 :: "r"(dst), "l"(src));
                }
            }
            asm volatile("cp.async.commit_group;");   // uniform group count
        }

        float sc512 = 512.0f * pend_sc;
        float epssc = (512.0f * EPSV) * pend_sc;
        E += pend_e; pend_e = 0; pend_sc = 1.0f;

        // pe from praw gathered last iteration (row t)
        float pe[KS];
        #pragma unroll
        for (int j = 0; j < KS; ++j)
            pe[j] = valid[j] ? fmaf(praw[j], sc512, epssc) : 0.0f;

        // Prefetch gather for step t+1 (row t+1 complete per wait above)
        int nslot = slot + 1; if (nslot == RS) nslot = 0;
        if (t + 1 < TN) {
            const float* row = rows[w][nslot];
            #pragma unroll
            for (int j = 0; j < KS; ++j) praw[j] = row[cls[j]];
        }
        slot = nslot;

        float h1 = __shfl_up_sync(FULL, a[KS - 1], 1);
        float h2 = __shfl_up_sync(FULL, a[KS - 2], 1);
        if (lane == 0) { h1 = 0.0f; h2 = 0.0f; }

        float n0 = (a[0] + h1   + (alw[0] ? h2   : 0.0f)) * pe[0];
        float n1 = (a[1] + a[0] + (alw[1] ? h1   : 0.0f)) * pe[1];
        float n2 = (a[2] + a[1] + (alw[2] ? a[0] : 0.0f)) * pe[2];
        float n3 = (a[3] + a[2] + (alw[3] ? a[1] : 0.0f)) * pe[3];
        float n4 = (a[4] + a[3] + (alw[4] ? a[2] : 0.0f)) * pe[4];
        a[0] = n0; a[1] = n1; a[2] = n2; a[3] = n3; a[4] = n4;

        if ((t & 7) == 0) {
            unsigned u = __float_as_uint(a[0]);
            u = max(u, __float_as_uint(a[1]));
            u = max(u, __float_as_uint(a[2]));
            u = max(u, __float_as_uint(a[3]));
            u = max(u, __float_as_uint(a[4]));
            u = __reduce_max_sync(FULL, u);
            int e = (int)(u >> 23) - 127;
            pend_e  = e;
            pend_sc = __uint_as_float((unsigned)(127 - e) << 23);  // 2^-e
        }

        if (t == T_eff - 1) {
            #pragma unroll
            for (int j = 0; j < KS; ++j)
                if (valid[j]) fin[w][KS * lane + j] = a[j];
            if (lane == 0) ecap_sh[w] = E;
        }
    }
    __syncwarp();

    if (lane == 0) {
        int ll = lab_len[b];
        int i1 = 2 * ll;
        int i2 = 2 * ll - 1;
        if (i1 < 0) i1 += SN;
        if (i2 < 0) i2 += SN;
        float x = fin[w][i1] + fin[w][i2];
        out[b] = -logf(x) + ((float)(9 * (T_eff - 1) - ecap_sh[w])) * LN2F;
    }
}

extern "C" void kernel_launch(void* const* d_in, const int* in_sizes, int n_in,
                              void* d_out, int out_size)
{
    const int*   y_true       = (const int*)d_in[0];
    const float* y_pred       = (const float*)d_in[1];
    const int*   input_length = (const int*)d_in[2];
    const int*   label_length = (const int*)d_in[3];
    float*       out          = (float*)d_out;

    ctc_w2_kernel<<<BN / 2, 64>>>(y_true, y_pred, input_length, label_length, out);
}

// round 9
// speedup vs baseline: 2.2236x; 1.3711x over previous
#include <cuda_runtime.h>
#include <math.h>

// B=256, T=512, C=512, L=64
#define BN 256
#define TN 512
#define CN 512
#define LN 64
#define SN 129              // 2L+1
#define BLANK 511
#define EPSV 1e-7f
#define RS 8                // row-ring slots
#define KS 5                // states per lane
#define LN2F 0.6931471805599453f
#define FULL 0xffffffffu

// CTC forward DP: one warp per batch element (round-4 structure: wait at
// loop top, inline gather, refill after syncwarp). Deltas vs round 4:
//  - blank-state gather deduplicated: one broadcast LDS of row[BLANK] plus
//    2-3 label LDS per lane (instead of 5 conflict-heavy gathers)
//  - neighbor shfls hoisted above wait_group (depend only on registers)
// Linear-space recursion with exact power-of-2 renorm (math identical to
// the log-space logsumexp recursion; rel_err unchanged).
__global__ __launch_bounds__(32, 8)
void ctc_warp3_kernel(const int* __restrict__ labels,     // [B, L]
                      const float* __restrict__ y_pred,   // [B, T, C]
                      const int* __restrict__ in_len,     // [B, 1]
                      const int* __restrict__ lab_len,    // [B, 1]
                      float* __restrict__ out)            // [B, 1]
{
    const int b    = blockIdx.x;
    const int lane = threadIdx.x;
    const bool oddlane = (lane & 1);

    __shared__ __align__(16) float rows[RS][CN];   // 16KB ring
    __shared__ float fin[SN];
    __shared__ int   ecap_sh;

    // Extended labels: state s = KS*lane + j ; s odd <-> label, parity of s
    // equals parity of (lane + j) since KS = 5 (odd).
    int  cls[KS];
    bool valid[KS];
    #pragma unroll
    for (int j = 0; j < KS; ++j) {
        int s = KS * lane + j;
        valid[j] = (s < SN);
        int c = BLANK;
        if (valid[j] && (s & 1)) c = labels[b * LN + (s >> 1)];
        cls[j] = valid[j] ? c : 0;
    }
    int cu2 = __shfl_up_sync(FULL, cls[KS - 2], 1);
    int cu1 = __shfl_up_sync(FULL, cls[KS - 1], 1);
    bool alw[KS];
    #pragma unroll
    for (int j = 0; j < KS; ++j) {
        int s   = KS * lane + j;
        int cm2 = (j >= 2) ? cls[j - 2] : ((j == 1) ? cu1 : cu2);
        alw[j] = valid[j] && (s >= 2) && (cls[j] != BLANK) && (cls[j] != cm2);
    }

    // Label-gather classes for this lane:
    //   even lane: labels at j = 1, 3          (third slot duplicates blank)
    //   odd  lane: labels at j = 0, 2, 4
    const int lc0 = oddlane ? cls[0] : cls[1];
    const int lc1 = oddlane ? cls[2] : cls[3];
    const int lc2 = oddlane ? cls[4] : BLANK;

    const float* base  = y_pred + (size_t)b * TN * CN;
    const int    T_eff = in_len[b];

    // t = 0
    float a[KS];
    #pragma unroll
    for (int j = 0; j < KS; ++j) {
        int s = KS * lane + j;
        a[j] = (s < 2) ? (base[cls[j]] + EPSV) : 0.0f;
    }
    if (T_eff == 1) {
        #pragma unroll
        for (int j = 0; j < KS; ++j)
            if (valid[j]) fin[KS * lane + j] = a[j];
        if (lane == 0) ecap_sh = 0;
    }

    // Prologue: rows 1..7 into ring, one commit group each
    #pragma unroll
    for (int st = 1; st < RS; ++st) {
        #pragma unroll
        for (int k = 0; k < 4; ++k) {
            unsigned dst = (unsigned)__cvta_generic_to_shared(
                &rows[st & (RS - 1)][lane * 4 + k * 128]);
            const float* src = base + (size_t)st * CN + lane * 4 + k * 128;
            asm volatile("cp.async.cg.shared.global [%0], [%1], 16;"
                         :: "r"(dst), "l"(src));
        }
        asm volatile("cp.async.commit_group;");
    }

    int   E = 0, pend_e = 0;
    float pend_sc = 1.0f;

    #pragma unroll 8
    for (int t = 1; t < TN; ++t) {
        // Neighbor halo from previous alpha — registers only, hoisted above
        // the memory wait so SHFL latency overlaps it.
        float h1 = __shfl_up_sync(FULL, a[KS - 1], 1);
        float h2 = __shfl_up_sync(FULL, a[KS - 2], 1);
        if (lane == 0) { h1 = 0.0f; h2 = 0.0f; }

        float sc512 = 512.0f * pend_sc;
        float epssc = (512.0f * EPSV) * pend_sc;
        E += pend_e; pend_e = 0; pend_sc = 1.0f;

        asm volatile("cp.async.wait_group %0;" :: "n"(RS - 2)); // row t done
        __syncwarp();

        // Gather: one broadcast blank + 3 label loads (dedup)
        const float* row = rows[t & (RS - 1)];
        float pb  = row[BLANK];
        float pl0 = row[lc0];
        float pl1 = row[lc1];
        float pl2 = row[lc2];

        // Refill slot (t-1)&7 with row t+7 (after syncwarp: WAR-safe)
        {
            int st = t + RS - 1;
            if (st < TN) {
                #pragma unroll
                for (int k = 0; k < 4; ++k) {
                    unsigned dst = (unsigned)__cvta_generic_to_shared(
                        &rows[st & (RS - 1)][lane * 4 + k * 128]);
                    const float* src = base + (size_t)st * CN + lane * 4 + k * 128;
                    asm volatile("cp.async.cg.shared.global [%0], [%1], 16;"
                                 :: "r"(dst), "l"(src));
                }
            }
            asm volatile("cp.async.commit_group;");  // uniform group count
        }

        // pe values (identical arithmetic per state as before)
        float pe_b = fmaf(pb,  sc512, epssc);
        float pe_0 = fmaf(pl0, sc512, epssc);
        float pe_1 = fmaf(pl1, sc512, epssc);
        float pe_2 = fmaf(pl2, sc512, epssc);

        float pe[KS];
        pe[0] = oddlane ? pe_0 : pe_b;
        pe[1] = oddlane ? pe_b : pe_0;
        pe[2] = oddlane ? pe_1 : pe_b;
        pe[3] = oddlane ? pe_b : pe_1;
        pe[4] = oddlane ? pe_2 : pe_b;
        #pragma unroll
        for (int j = 0; j < KS; ++j)
            if (!valid[j]) pe[j] = 0.0f;

        float n0 = (a[0] + h1   + (alw[0] ? h2   : 0.0f)) * pe[0];
        float n1 = (a[1] + a[0] + (alw[1] ? h1   : 0.0f)) * pe[1];
        float n2 = (a[2] + a[1] + (alw[2] ? a[0] : 0.0f)) * pe[2];
        float n3 = (a[3] + a[2] + (alw[3] ? a[1] : 0.0f)) * pe[3];
        float n4 = (a[4] + a[3] + (alw[4] ? a[2] : 0.0f)) * pe[4];
        a[0] = n0; a[1] = n1; a[2] = n2; a[3] = n3; a[4] = n4;

        if ((t & 7) == 0) {
            unsigned u = __float_as_uint(a[0]);
            u = max(u, __float_as_uint(a[1]));
            u = max(u, __float_as_uint(a[2]));
            u = max(u, __float_as_uint(a[3]));
            u = max(u, __float_as_uint(a[4]));
            u = __reduce_max_sync(FULL, u);
            int e = (int)(u >> 23) - 127;
            pend_e  = e;
            pend_sc = __uint_as_float((unsigned)(127 - e) << 23);  // 2^-e exact
        }

        if (t == T_eff - 1) {
            #pragma unroll
            for (int j = 0; j < KS; ++j)
                if (valid[j]) fin[KS * lane + j] = a[j];
            if (lane == 0) ecap_sh = E;
        }
    }
    __syncwarp();

    if (lane == 0) {
        int ll = lab_len[b];
        int i1 = 2 * ll;
        int i2 = 2 * ll - 1;
        if (i1 < 0) i1 += SN;
        if (i2 < 0) i2 += SN;
        float x = fin[i1] + fin[i2];
        // stored = true * 2^(9*(T_eff-1) - ecap)
        out[b] = -logf(x) + ((float)(9 * (T_eff - 1) - ecap_sh)) * LN2F;
    }
}

extern "C" void kernel_launch(void* const* d_in, const int* in_sizes, int n_in,
                              void* d_out, int out_size)
{
    const int*   y_true       = (const int*)d_in[0];
    const float* y_pred       = (const float*)d_in[1];
    const int*   input_length = (const int*)d_in[2];
    const int*   label_length = (const int*)d_in[3];
    float*       out          = (float*)d_out;

    ctc_warp3_kernel<<<BN, 32>>>(y_true, y_pred, input_length, label_length, out);
}

// round 10
// speedup vs baseline: 2.8065x; 1.2621x over previous
#include <cuda_runtime.h>
#include <math.h>

// B=256, T=512, C=512, L=64
#define BN 256
#define TN 512
#define CN 512
#define LN 64
#define SN 129              // 2L+1
#define BLANK 511
#define EPSV 1e-7f
#define RS 16               // row-ring slots (DOUBLED: 14 groups in flight)
#define KS 5                // states per lane
#define LN2F 0.6931471805599453f
#define FULL 0xffffffffu

// CTC forward DP: one warp per batch element (round-9 structure verbatim;
// only change: ring depth 8 -> 16 so 14 cp.async groups stay outstanding,
// covering DRAM round-trip latency). Alpha in registers (5/lane),
// neighbors via shfl, blank-deduplicated smem gather.
// Linear-space recursion + exact power-of-2 renorm (math identical to
// log-space logsumexp; rel_err unchanged).
__global__ __launch_bounds__(32, 4)
void ctc_warp4_kernel(const int* __restrict__ labels,     // [B, L]
                      const float* __restrict__ y_pred,   // [B, T, C]
                      const int* __restrict__ in_len,     // [B, 1]
                      const int* __restrict__ lab_len,    // [B, 1]
                      float* __restrict__ out)            // [B, 1]
{
    const int b    = blockIdx.x;
    const int lane = threadIdx.x;
    const bool oddlane = (lane & 1);

    __shared__ __align__(16) float rows[RS][CN];   // 32KB ring
    __shared__ float fin[SN];
    __shared__ int   ecap_sh;

    // Extended labels: state s = KS*lane + j ; parity of s = parity of lane+j
    int  cls[KS];
    bool valid[KS];
    #pragma unroll
    for (int j = 0; j < KS; ++j) {
        int s = KS * lane + j;
        valid[j] = (s < SN);
        int c = BLANK;
        if (valid[j] && (s & 1)) c = labels[b * LN + (s >> 1)];
        cls[j] = valid[j] ? c : 0;
    }
    int cu2 = __shfl_up_sync(FULL, cls[KS - 2], 1);
    int cu1 = __shfl_up_sync(FULL, cls[KS - 1], 1);
    bool alw[KS];
    #pragma unroll
    for (int j = 0; j < KS; ++j) {
        int s   = KS * lane + j;
        int cm2 = (j >= 2) ? cls[j - 2] : ((j == 1) ? cu1 : cu2);
        alw[j] = valid[j] && (s >= 2) && (cls[j] != BLANK) && (cls[j] != cm2);
    }

    // Label-gather classes (blank handled once via broadcast)
    const int lc0 = oddlane ? cls[0] : cls[1];
    const int lc1 = oddlane ? cls[2] : cls[3];
    const int lc2 = oddlane ? cls[4] : BLANK;

    const float* base  = y_pred + (size_t)b * TN * CN;
    const int    T_eff = in_len[b];

    // t = 0
    float a[KS];
    #pragma unroll
    for (int j = 0; j < KS; ++j) {
        int s = KS * lane + j;
        a[j] = (s < 2) ? (base[cls[j]] + EPSV) : 0.0f;
    }
    if (T_eff == 1) {
        #pragma unroll
        for (int j = 0; j < KS; ++j)
            if (valid[j]) fin[KS * lane + j] = a[j];
        if (lane == 0) ecap_sh = 0;
    }

    // Prologue: rows 1..RS-1 into ring, one commit group each
    #pragma unroll
    for (int st = 1; st < RS; ++st) {
        #pragma unroll
        for (int k = 0; k < 4; ++k) {
            unsigned dst = (unsigned)__cvta_generic_to_shared(
                &rows[st & (RS - 1)][lane * 4 + k * 128]);
            const float* src = base + (size_t)st * CN + lane * 4 + k * 128;
            asm volatile("cp.async.cg.shared.global [%0], [%1], 16;"
                         :: "r"(dst), "l"(src));
        }
        asm volatile("cp.async.commit_group;");
    }

    int   E = 0, pend_e = 0;
    float pend_sc = 1.0f;

    #pragma unroll 8
    for (int t = 1; t < TN; ++t) {
        // Halo from previous alpha (registers only) — overlaps the wait
        float h1 = __shfl_up_sync(FULL, a[KS - 1], 1);
        float h2 = __shfl_up_sync(FULL, a[KS - 2], 1);
        if (lane == 0) { h1 = 0.0f; h2 = 0.0f; }

        float sc512 = 512.0f * pend_sc;
        float epssc = (512.0f * EPSV) * pend_sc;
        E += pend_e; pend_e = 0; pend_sc = 1.0f;

        asm volatile("cp.async.wait_group %0;" :: "n"(RS - 2)); // row t done
        __syncwarp();

        // Gather: one broadcast blank + 3 label loads (deduplicated)
        const float* row = rows[t & (RS - 1)];
        float pb  = row[BLANK];
        float pl0 = row[lc0];
        float pl1 = row[lc1];
        float pl2 = row[lc2];

        // Refill slot (t-1)&(RS-1) with row t+RS-1 (WAR-safe after syncwarp)
        {
            int st = t + RS - 1;
            if (st < TN) {
                #pragma unroll
                for (int k = 0; k < 4; ++k) {
                    unsigned dst = (unsigned)__cvta_generic_to_shared(
                        &rows[st & (RS - 1)][lane * 4 + k * 128]);
                    const float* src = base + (size_t)st * CN + lane * 4 + k * 128;
                    asm volatile("cp.async.cg.shared.global [%0], [%1], 16;"
                                 :: "r"(dst), "l"(src));
                }
            }
            asm volatile("cp.async.commit_group;");  // uniform group count
        }

        float pe_b = fmaf(pb,  sc512, epssc);
        float pe_0 = fmaf(pl0, sc512, epssc);
        float pe_1 = fmaf(pl1, sc512, epssc);
        float pe_2 = fmaf(pl2, sc512, epssc);

        float pe[KS];
        pe[0] = oddlane ? pe_0 : pe_b;
        pe[1] = oddlane ? pe_b : pe_0;
        pe[2] = oddlane ? pe_1 : pe_b;
        pe[3] = oddlane ? pe_b : pe_1;
        pe[4] = oddlane ? pe_2 : pe_b;
        #pragma unroll
        for (int j = 0; j < KS; ++j)
            if (!valid[j]) pe[j] = 0.0f;

        float n0 = (a[0] + h1   + (alw[0] ? h2   : 0.0f)) * pe[0];
        float n1 = (a[1] + a[0] + (alw[1] ? h1   : 0.0f)) * pe[1];
        float n2 = (a[2] + a[1] + (alw[2] ? a[0] : 0.0f)) * pe[2];
        float n3 = (a[3] + a[2] + (alw[3] ? a[1] : 0.0f)) * pe[3];
        float n4 = (a[4] + a[3] + (alw[4] ? a[2] : 0.0f)) * pe[4];
        a[0] = n0; a[1] = n1; a[2] = n2; a[3] = n3; a[4] = n4;

        if ((t & 7) == 0) {
            unsigned u = __float_as_uint(a[0]);
            u = max(u, __float_as_uint(a[1]));
            u = max(u, __float_as_uint(a[2]));
            u = max(u, __float_as_uint(a[3]));
            u = max(u, __float_as_uint(a[4]));
            u = __reduce_max_sync(FULL, u);
            int e = (int)(u >> 23) - 127;
            pend_e  = e;
            pend_sc = __uint_as_float((unsigned)(127 - e) << 23);  // 2^-e exact
        }

        if (t == T_eff - 1) {
            #pragma unroll
            for (int j = 0; j < KS; ++j)
                if (valid[j]) fin[KS * lane + j] = a[j];
            if (lane == 0) ecap_sh = E;
        }
    }
    __syncwarp();

    if (lane == 0) {
        int ll = lab_len[b];
        int i1 = 2 * ll;
        int i2 = 2 * ll - 1;
        if (i1 < 0) i1 += SN;
        if (i2 < 0) i2 += SN;
        float x = fin[i1] + fin[i2];
        // stored = true * 2^(9*(T_eff-1) - ecap)
        out[b] = -logf(x) + ((float)(9 * (T_eff - 1) - ecap_sh)) * LN2F;
    }
}

extern "C" void kernel_launch(void* const* d_in, const int* in_sizes, int n_in,
                              void* d_out, int out_size)
{
    const int*   y_true       = (const int*)d_in[0];
    const float* y_pred       = (const float*)d_in[1];
    const int*   input_length = (const int*)d_in[2];
    const int*   label_length = (const int*)d_in[3];
    float*       out          = (float*)d_out;

    ctc_warp4_kernel<<<BN, 32>>>(y_true, y_pred, input_length, label_length, out);
}